// round 4
// baseline (speedup 1.0000x reference)
#include <cuda_runtime.h>
#include <cstdint>

// ============================ problem constants ============================
#define BB 4
#define NN 4096
#define FF 128
#define KT 32                    // K per pipeline stage
#define NSTG 4
#define KITERS (NN / KT)         // 128

// ====================== smem layout (float offsets) =======================
#define SM_DEG   0                                  // 128 floats: 1/deg
#define SM_STG   256
#define STG_FL   9216                               // A 128x36 + B 128x36
#define SM_A(s)  (SM_STG + (s) * STG_FL)
#define SM_B(s)  (SM_A(s) + 4608)
#define SM_Y     256                                // epilogue reuses stages
#define SM_W     (SM_Y + 16896)                     // 128 x 132
#define SMEM_FL  (SM_STG + NSTG * STG_FL)           // 37120 floats = 148480 B

// scratch (allocation-free rule: __device__ globals)
__device__ __align__(16) float g_xt[(size_t)BB * FF * NN];   // Xt[b][f][k]
__device__ __align__(16) float g_wt[FF * FF];                // wt[n][k]

// ============================ helpers ============================
__device__ __forceinline__ uint32_t smem_to_u32(const void* p) {
    uint32_t a;
    asm("{ .reg .u64 tmp; cvta.to.shared.u64 tmp, %1; cvt.u32.u64 %0, tmp; }"
        : "=r"(a) : "l"(p));
    return a;
}

__device__ __forceinline__ void cp16(uint32_t s, const float* g) {
    asm volatile("cp.async.cg.shared.global [%0], [%1], 16;" :: "r"(s), "l"(g));
}

__device__ __forceinline__ uint32_t f2tf(float x) {   // round-to-nearest tf32
    uint32_t r;
    asm("cvt.rna.tf32.f32 %0, %1;" : "=r"(r) : "f"(x));
    return r;
}

__device__ __forceinline__ float tf32r(float x) { return __uint_as_float(f2tf(x)); }

// D += A(16x8) * B(8x8), tf32 inputs, fp32 accum
#define MMA8(d, a, b) \
    asm volatile("mma.sync.aligned.m16n8k8.row.col.f32.tf32.tf32.f32 " \
        "{%0,%1,%2,%3}, {%4,%5,%6,%7}, {%8,%9}, {%0,%1,%2,%3};" \
        : "+f"((d)[0]), "+f"((d)[1]), "+f"((d)[2]), "+f"((d)[3]) \
        : "r"((a)[0]), "r"((a)[1]), "r"((a)[2]), "r"((a)[3]), \
          "r"((b)[0]), "r"((b)[1]))

// ============================ prologue kernels ============================
// Xt[b][f][k] = round_tf32(X[b][k][f])
__global__ void transpose_x_kernel(const float* __restrict__ x) {
    __shared__ float t[32][33];
    int b = blockIdx.z, f0 = blockIdx.y * 32, k0 = blockIdx.x * 32;
    int tx = threadIdx.x, ty = threadIdx.y;
    t[ty][tx] = x[((size_t)b * NN + (k0 + ty)) * FF + (f0 + tx)];
    __syncthreads();
    g_xt[((size_t)b * FF + (f0 + ty)) * NN + (k0 + tx)] = tf32r(t[tx][ty]);
}

// wt[n][k] = round_tf32(w[k][n])
__global__ void transpose_w_kernel(const float* __restrict__ w) {
    __shared__ float t[32][33];
    int n0 = blockIdx.y * 32, k0 = blockIdx.x * 32;
    int tx = threadIdx.x, ty = threadIdx.y;
    t[ty][tx] = w[(k0 + ty) * FF + (n0 + tx)];
    __syncthreads();
    g_wt[(n0 + ty) * FF + (k0 + tx)] = tf32r(t[tx][ty]);
}

// ============================ main kernel ============================
// grid = 128 CTAs (4 batches x 32 M-tiles), 256 threads = 8 warps (4x2),
// warp tile 32(M) x 64(N). cp.async 4-stage pipeline, mma.sync tf32.
__global__ void __launch_bounds__(256, 1)
graphconv_main(const float* __restrict__ A, const float* __restrict__ X,
               float* __restrict__ out) {
    extern __shared__ __align__(16) float sm[];
    const uint32_t sbase = smem_to_u32(sm);
    const int tid = threadIdx.x;
    const int lane = tid & 31, warp = tid >> 5;
    const int g = lane >> 2, t = lane & 3;          // mma group / thread-in-group
    const int wr = warp >> 1, wc = warp & 1;        // warp grid 4x2
    const int bb = blockIdx.x >> 5;
    const int row0 = (blockIdx.x & 31) << 7;

    const float* Ab = A + (size_t)bb * NN * NN + (size_t)row0 * NN;
    const float* Xt = g_xt + (size_t)bb * FF * NN;

    auto issue = [&](int chunk, int s) {
        const int k0 = chunk * KT;
        #pragma unroll
        for (int i = 0; i < 4; i++) {
            int c = tid + 256 * i, r = c >> 3, cc = c & 7;
            cp16(sbase + (uint32_t)(SM_A(s) + r * 36 + cc * 4) * 4u,
                 Ab + (size_t)r * NN + k0 + cc * 4);
        }
        #pragma unroll
        for (int i = 0; i < 4; i++) {
            int c = tid + 256 * i, r = c >> 3, cc = c & 7;
            cp16(sbase + (uint32_t)(SM_B(s) + r * 36 + cc * 4) * 4u,
                 Xt + (size_t)r * NN + k0 + cc * 4);
        }
        asm volatile("cp.async.commit_group;");
    };

    float acc[2][8][4];
    #pragma unroll
    for (int mi = 0; mi < 2; mi++)
        #pragma unroll
        for (int ni = 0; ni < 8; ni++)
            #pragma unroll
            for (int q = 0; q < 4; q++) acc[mi][ni][q] = 0.f;

    float dsum = 0.f;
    const int drow = tid >> 1, dh = tid & 1;

    issue(0, 0); issue(1, 1); issue(2, 2);

    for (int k = 0; k < KITERS; k++) {
        const int s = k & 3;
        asm volatile("cp.async.wait_group 2;");
        __syncthreads();
        const float* sa = sm + SM_A(s);
        const float* sb = sm + SM_B(s);

        // deg partial row-sum (raw fp32 A) — half a row per thread
        {
            const float4* dp =
                reinterpret_cast<const float4*>(sa + drow * 36 + dh * 16);
            #pragma unroll
            for (int j = 0; j < 4; j++) {
                float4 v = dp[(j + drow) & 3];
                dsum += (v.x + v.y) + (v.z + v.w);
            }
        }

        #pragma unroll
        for (int ks = 0; ks < 4; ks++) {
            const int kk = ks * 8;
            uint32_t af[2][4];
            #pragma unroll
            for (int mi = 0; mi < 2; mi++) {
                const float* ap = sa + (wr * 32 + mi * 16 + g) * 36 + kk + t;
                af[mi][0] = f2tf(ap[0]);
                af[mi][1] = f2tf(ap[8 * 36]);
                af[mi][2] = f2tf(ap[4]);
                af[mi][3] = f2tf(ap[8 * 36 + 4]);
            }
            uint32_t bf[8][2];
            #pragma unroll
            for (int ni = 0; ni < 8; ni++) {
                const float* bp = sb + (wc * 64 + ni * 8 + g) * 36 + kk + t;
                bf[ni][0] = __float_as_uint(bp[0]);   // pre-rounded tf32
                bf[ni][1] = __float_as_uint(bp[4]);
            }
            #pragma unroll
            for (int mi = 0; mi < 2; mi++)
                #pragma unroll
                for (int ni = 0; ni < 8; ni++)
                    MMA8(acc[mi][ni], af[mi], bf[ni]);
        }

        if (k + 3 < KITERS) issue(k + 3, (k + 3) & 3);
        else asm volatile("cp.async.commit_group;");  // keep group count rolling
    }

    // deg = rowsum(A) + 1 ; store reciprocal
    dsum += __shfl_xor_sync(0xffffffffu, dsum, 1);
    if (dh == 0) sm[SM_DEG + drow] = 1.0f / (dsum + 1.0f);
    __syncthreads();      // all MMA reads done -> safe to overwrite stages with Y

    // Y = AX + X, rounded to tf32, staged for GEMM2 (stride 132 floats)
    {
        const float* Xrow = X + ((size_t)bb * NN + row0) * FF;
        uint32_t* yw = reinterpret_cast<uint32_t*>(sm + SM_Y);
        #pragma unroll
        for (int mi = 0; mi < 2; mi++) {
            int r0 = wr * 32 + mi * 16 + g;
            #pragma unroll
            for (int ni = 0; ni < 8; ni++) {
                int n = wc * 64 + ni * 8 + 2 * t;
                float2 x0 = *reinterpret_cast<const float2*>(
                    Xrow + (size_t)r0 * FF + n);
                float2 x1 = *reinterpret_cast<const float2*>(
                    Xrow + (size_t)(r0 + 8) * FF + n);
                yw[r0 * 132 + n]           = f2tf(acc[mi][ni][0] + x0.x);
                yw[r0 * 132 + n + 1]       = f2tf(acc[mi][ni][1] + x0.y);
                yw[(r0 + 8) * 132 + n]     = f2tf(acc[mi][ni][2] + x1.x);
                yw[(r0 + 8) * 132 + n + 1] = f2tf(acc[mi][ni][3] + x1.y);
            }
        }
    }
    // stage wt (pre-rounded) into smem
    #pragma unroll
    for (int i = tid; i < 4096; i += 256) {
        int n = i >> 5, kq = (i & 31) * 4;
        float4 v = *reinterpret_cast<const float4*>(g_wt + i * 4);
        *reinterpret_cast<float4*>(sm + SM_W + n * 132 + kq) = v;
    }
    __syncthreads();

    // GEMM2: Z = Y @ w  (K = 128 -> 16 k8 steps)
    float acc2[2][8][4];
    #pragma unroll
    for (int mi = 0; mi < 2; mi++)
        #pragma unroll
        for (int ni = 0; ni < 8; ni++)
            #pragma unroll
            for (int q = 0; q < 4; q++) acc2[mi][ni][q] = 0.f;

    const float* ya = sm + SM_Y;
    const float* wb = sm + SM_W;
    #pragma unroll 4
    for (int ks = 0; ks < 16; ks++) {
        const int kk = ks * 8;
        uint32_t af[2][4];
        #pragma unroll
        for (int mi = 0; mi < 2; mi++) {
            const float* ap = ya + (wr * 32 + mi * 16 + g) * 132 + kk + t;
            af[mi][0] = __float_as_uint(ap[0]);
            af[mi][1] = __float_as_uint(ap[8 * 132]);
            af[mi][2] = __float_as_uint(ap[4]);
            af[mi][3] = __float_as_uint(ap[8 * 132 + 4]);
        }
        uint32_t bf[8][2];
        #pragma unroll
        for (int ni = 0; ni < 8; ni++) {
            const float* bp = wb + (wc * 64 + ni * 8 + g) * 132 + kk + t;
            bf[ni][0] = __float_as_uint(bp[0]);
            bf[ni][1] = __float_as_uint(bp[4]);
        }
        #pragma unroll
        for (int mi = 0; mi < 2; mi++)
            #pragma unroll
            for (int ni = 0; ni < 8; ni++)
                MMA8(acc2[mi][ni], af[mi], bf[ni]);
    }

    // out = relu(Z) * (1/deg)
    {
        float rc[2][2];
        #pragma unroll
        for (int mi = 0; mi < 2; mi++) {
            rc[mi][0] = sm[SM_DEG + wr * 32 + mi * 16 + g];
            rc[mi][1] = sm[SM_DEG + wr * 32 + mi * 16 + g + 8];
        }
        float* ob = out + ((size_t)bb * NN + row0) * FF;
        #pragma unroll
        for (int mi = 0; mi < 2; mi++) {
            int r0 = wr * 32 + mi * 16 + g;
            #pragma unroll
            for (int ni = 0; ni < 8; ni++) {
                int n = wc * 64 + ni * 8 + 2 * t;
                float2 v0, v1;
                v0.x = fmaxf(acc2[mi][ni][0], 0.f) * rc[mi][0];
                v0.y = fmaxf(acc2[mi][ni][1], 0.f) * rc[mi][0];
                v1.x = fmaxf(acc2[mi][ni][2], 0.f) * rc[mi][1];
                v1.y = fmaxf(acc2[mi][ni][3], 0.f) * rc[mi][1];
                *reinterpret_cast<float2*>(ob + (size_t)r0 * FF + n) = v0;
                *reinterpret_cast<float2*>(ob + (size_t)(r0 + 8) * FF + n) = v1;
            }
        }
    }
}

// ============================ host ============================
extern "C" void kernel_launch(void* const* d_in, const int* in_sizes, int n_in,
                              void* d_out, int out_size) {
    const float* A = (const float*)d_in[0];   // relation_matrix [4,4096,4096]
    const float* X = (const float*)d_in[1];   // inputs          [4,4096,128]
    const float* w = (const float*)d_in[2];   // w               [128,128]
    float* out = (float*)d_out;               // [4,4096,128] fp32

    cudaFuncSetAttribute(graphconv_main,
                         cudaFuncAttributeMaxDynamicSharedMemorySize,
                         SMEM_FL * 4);

    transpose_x_kernel<<<dim3(NN / 32, FF / 32, BB), dim3(32, 32)>>>(X);
    transpose_w_kernel<<<dim3(FF / 32, FF / 32), dim3(32, 32)>>>(w);
    graphconv_main<<<BB * 32, 256, SMEM_FL * 4>>>(A, X, out);
}

// round 6
// speedup vs baseline: 1.4419x; 1.4419x over previous
#include <cuda_runtime.h>
#include <cuda_fp16.h>
#include <cstdint>

// ============================ problem constants ============================
#define BB 4
#define NN 4096
#define FF 128
#define KT 32                    // K per pipeline stage
#define NSTG 4
#define KITERS (NN / KT)         // 128

// ====================== main-kernel smem layout (bytes) ===================
// A stage: 128 rows x 40 floats (32 data + 8 pad) = 20480 B
// B stage: 128 rows x 40 halves (32 data + 8 pad) = 10240 B
#define SM_DEG    0
#define SM_STG    512
#define STG_BYT   30720
#define SM_A(s)   (SM_STG + (s) * STG_BYT)
#define SM_B(s)   (SM_A(s) + 20480)
#define SMEM_MAIN (SM_STG + NSTG * STG_BYT)        // 123392 B

// scratch (allocation-free rule: __device__ globals)
__device__ __align__(16) __half g_xw [(size_t)BB * NN * FF];  // Xw[b][k][n]
__device__ __align__(16) __half g_xwt[(size_t)BB * FF * NN];  // Xwt[b][n][k]

// ============================ helpers ============================
__device__ __forceinline__ uint32_t smem_to_u32(const void* p) {
    uint32_t a;
    asm("{ .reg .u64 tmp; cvta.to.shared.u64 tmp, %1; cvt.u32.u64 %0, tmp; }"
        : "=r"(a) : "l"(p));
    return a;
}

__device__ __forceinline__ void cp16(uint32_t s, const void* g) {
    asm volatile("cp.async.cg.shared.global [%0], [%1], 16;" :: "r"(s), "l"(g));
}

// pack two fp32 -> f16x2 reg, lo in low half (round-to-nearest-even)
__device__ __forceinline__ uint32_t packh2(float lo, float hi) {
    uint32_t r;
    asm("cvt.rn.f16x2.f32 %0, %1, %2;" : "=r"(r) : "f"(hi), "f"(lo));
    return r;
}

// D += A(16x16) * B(16x8), fp16 inputs, fp32 accum
#define MMA16(d, a, b) \
    asm volatile("mma.sync.aligned.m16n8k16.row.col.f32.f16.f16.f32 " \
        "{%0,%1,%2,%3}, {%4,%5,%6,%7}, {%8,%9}, {%0,%1,%2,%3};" \
        : "+f"((d)[0]), "+f"((d)[1]), "+f"((d)[2]), "+f"((d)[3]) \
        : "r"((a)[0]), "r"((a)[1]), "r"((a)[2]), "r"((a)[3]), \
          "r"((b)[0]), "r"((b)[1]))

// ============================ prep kernel ============================
// Computes Xw = X @ w (fp16 mma, fp32 accum) for a 128-row k-tile and writes
// both layouts: g_xw[b][k][n] and g_xwt[b][n][k] (fp16).
// grid (32, BB), 256 threads = 8 warps (4x2), warp tile 32(k) x 64(n).
#define PX_STRIDE 136            // halves per row (128 data + 8 pad)
__global__ void __launch_bounds__(256, 1)
prep_xw_kernel(const float* __restrict__ X, const float* __restrict__ w) {
    extern __shared__ __align__(16) char psm[];
    __half* smx = reinterpret_cast<__half*>(psm);                  // X tile
    __half* smw = reinterpret_cast<__half*>(psm) + 128 * PX_STRIDE; // wt[n][f]
    const int tid = threadIdx.x;
    const int lane = tid & 31, warp = tid >> 5;
    const int g = lane >> 2, t = lane & 3;
    const int wr = warp >> 1, wc = warp & 1;
    const int b = blockIdx.y, k0 = blockIdx.x * 128;

    // X tile -> fp16 smem (row-major [k][f])
    const float2* xp = reinterpret_cast<const float2*>(
        X + ((size_t)b * NN + k0) * FF);
    #pragma unroll
    for (int i = 0; i < 32; i++) {
        int idx = tid + 256 * i;             // 8192 float2
        int k = idx >> 6, f2i = idx & 63;
        float2 v = xp[(size_t)k * 64 + f2i];
        *reinterpret_cast<__half2*>(smx + k * PX_STRIDE + f2i * 2) =
            __float22half2_rn(v);
    }
    // w -> fp16 smem transposed (wt[n][f] = w[f][n])
    #pragma unroll
    for (int i = 0; i < 32; i++) {
        int idx = tid + 256 * i;             // 8192 float2
        int f = idx >> 6, n = (idx & 63) * 2;
        float2 v = *reinterpret_cast<const float2*>(w + (size_t)f * FF + n);
        smw[(n + 0) * PX_STRIDE + f] = __float2half_rn(v.x);
        smw[(n + 1) * PX_STRIDE + f] = __float2half_rn(v.y);
    }
    __syncthreads();

    float acc[2][8][4];
    #pragma unroll
    for (int mi = 0; mi < 2; mi++)
        #pragma unroll
        for (int ni = 0; ni < 8; ni++)
            #pragma unroll
            for (int q = 0; q < 4; q++) acc[mi][ni][q] = 0.f;

    #pragma unroll
    for (int ks = 0; ks < 8; ks++) {
        const int kk = ks * 16;
        uint32_t af[2][4];
        #pragma unroll
        for (int mi = 0; mi < 2; mi++) {
            const __half* ap = smx + (wr * 32 + mi * 16 + g) * PX_STRIDE + kk + 2 * t;
            af[mi][0] = *reinterpret_cast<const uint32_t*>(ap);
            af[mi][1] = *reinterpret_cast<const uint32_t*>(ap + 8 * PX_STRIDE);
            af[mi][2] = *reinterpret_cast<const uint32_t*>(ap + 8);
            af[mi][3] = *reinterpret_cast<const uint32_t*>(ap + 8 * PX_STRIDE + 8);
        }
        uint32_t bf[8][2];
        #pragma unroll
        for (int ni = 0; ni < 8; ni++) {
            const __half* bp = smw + (wc * 64 + ni * 8 + g) * PX_STRIDE + kk + 2 * t;
            bf[ni][0] = *reinterpret_cast<const uint32_t*>(bp);
            bf[ni][1] = *reinterpret_cast<const uint32_t*>(bp + 8);
        }
        #pragma unroll
        for (int mi = 0; mi < 2; mi++)
            #pragma unroll
            for (int ni = 0; ni < 8; ni++)
                MMA16(acc[mi][ni], af[mi], bf[ni]);
    }

    // write Xw[b][k][n] (fp16, coalesced) and stage to smem for transpose
    __half* xwg = g_xw + ((size_t)b * NN + k0) * FF;
    __syncthreads();                       // done reading smx -> reuse it
    #pragma unroll
    for (int mi = 0; mi < 2; mi++) {
        int r0 = wr * 32 + mi * 16 + g;
        #pragma unroll
        for (int ni = 0; ni < 8; ni++) {
            int n = wc * 64 + ni * 8 + 2 * t;
            __half2 h0, h1;
            h0 = __floats2half2_rn(acc[mi][ni][0], acc[mi][ni][1]);
            h1 = __floats2half2_rn(acc[mi][ni][2], acc[mi][ni][3]);
            *reinterpret_cast<__half2*>(xwg + (size_t)r0 * FF + n) = h0;
            *reinterpret_cast<__half2*>(xwg + (size_t)(r0 + 8) * FF + n) = h1;
            *reinterpret_cast<__half2*>(smx + r0 * PX_STRIDE + n) = h0;
            *reinterpret_cast<__half2*>(smx + (r0 + 8) * PX_STRIDE + n) = h1;
        }
    }
    __syncthreads();
    // transposed write Xwt[b][n][k0+kk]
    __half* xwtg = g_xwt + (size_t)b * FF * NN + k0;
    #pragma unroll
    for (int i = 0; i < 64; i++) {
        int idx = tid + 256 * i;             // 16384 halves
        int n = idx >> 7, kk = idx & 127;
        xwtg[(size_t)n * NN + kk] = smx[kk * PX_STRIDE + n];
    }
}

// ============================ main kernel ============================
// grid = 128 CTAs (4 batches x 32 M-tiles), 256 threads = 8 warps (4x2),
// warp tile 32(M) x 64(N). cp.async 4-stage pipeline, mma.sync fp16 k16.
__global__ void __launch_bounds__(256, 1)
graphconv_main(const float* __restrict__ A, float* __restrict__ out) {
    extern __shared__ __align__(16) char smc[];
    float* sm = reinterpret_cast<float*>(smc);
    const uint32_t sbase = smem_to_u32(smc);
    const int tid = threadIdx.x;
    const int lane = tid & 31, warp = tid >> 5;
    const int g = lane >> 2, t = lane & 3;
    const int wr = warp >> 1, wc = warp & 1;
    const int bb = blockIdx.x >> 5;
    const int row0 = (blockIdx.x & 31) << 7;

    const float* Ab = A + (size_t)bb * NN * NN + (size_t)row0 * NN;
    const __half* Xwt = g_xwt + (size_t)bb * FF * NN;

    auto issue = [&](int chunk, int s) {
        const int k0 = chunk * KT;
        #pragma unroll
        for (int i = 0; i < 4; i++) {        // A: 128 rows x 128 B
            int c = tid + 256 * i, r = c >> 3, cc = c & 7;
            cp16(sbase + SM_A(s) + r * 160 + cc * 16,
                 Ab + (size_t)r * NN + k0 + cc * 4);
        }
        #pragma unroll
        for (int i = 0; i < 2; i++) {        // B: 128 rows x 64 B (fp16)
            int c = tid + 256 * i, r = c >> 2, cc = c & 3;
            cp16(sbase + SM_B(s) + r * 80 + cc * 16,
                 Xwt + (size_t)r * NN + k0 + cc * 8);
        }
        asm volatile("cp.async.commit_group;");
    };

    float acc[2][8][4];
    #pragma unroll
    for (int mi = 0; mi < 2; mi++)
        #pragma unroll
        for (int ni = 0; ni < 8; ni++)
            #pragma unroll
            for (int q = 0; q < 4; q++) acc[mi][ni][q] = 0.f;

    float dsum = 0.f;
    const int drow = tid >> 1, dh = tid & 1;

    issue(0, 0); issue(1, 1); issue(2, 2);

    for (int k = 0; k < KITERS; k++) {
        const int s = k & 3;
        asm volatile("cp.async.wait_group 2;");
        __syncthreads();
        const float* sa = sm + (SM_A(s) >> 2);
        const __half* sb = reinterpret_cast<const __half*>(smc + SM_B(s));

        // deg partial row-sum (raw fp32 A) — half a row per thread
        {
            const float4* dp =
                reinterpret_cast<const float4*>(sa + drow * 40 + dh * 16);
            #pragma unroll
            for (int j = 0; j < 4; j++) {
                float4 v = dp[(j + drow) & 3];
                dsum += (v.x + v.y) + (v.z + v.w);
            }
        }

        #pragma unroll
        for (int ks = 0; ks < 2; ks++) {
            const int kk = ks * 16;
            uint32_t af[2][4];
            #pragma unroll
            for (int mi = 0; mi < 2; mi++) {
                const float* ap = sa + (wr * 32 + mi * 16 + g) * 40 + kk + 2 * t;
                float2 v0 = *reinterpret_cast<const float2*>(ap);
                float2 v1 = *reinterpret_cast<const float2*>(ap + 8 * 40);
                float2 v2 = *reinterpret_cast<const float2*>(ap + 8);
                float2 v3 = *reinterpret_cast<const float2*>(ap + 8 * 40 + 8);
                af[mi][0] = packh2(v0.x, v0.y);
                af[mi][1] = packh2(v1.x, v1.y);
                af[mi][2] = packh2(v2.x, v2.y);
                af[mi][3] = packh2(v3.x, v3.y);
            }
            uint32_t bf[8][2];
            #pragma unroll
            for (int ni = 0; ni < 8; ni++) {
                const __half* bp = sb + (wc * 64 + ni * 8 + g) * 40 + kk + 2 * t;
                bf[ni][0] = *reinterpret_cast<const uint32_t*>(bp);
                bf[ni][1] = *reinterpret_cast<const uint32_t*>(bp + 8);
            }
            #pragma unroll
            for (int mi = 0; mi < 2; mi++)
                #pragma unroll
                for (int ni = 0; ni < 8; ni++)
                    MMA16(acc[mi][ni], af[mi], bf[ni]);
        }

        if (k + 3 < KITERS) issue(k + 3, (k + 3) & 3);
        else asm volatile("cp.async.commit_group;");  // keep group count rolling
    }

    // deg = rowsum(A) + 1 ; store reciprocal
    dsum += __shfl_xor_sync(0xffffffffu, dsum, 1);
    if (dh == 0) sm[(SM_DEG >> 2) + drow] = 1.0f / (dsum + 1.0f);
    __syncthreads();

    // out = relu(acc + Xw) * (1/deg)
    {
        float rc[2][2];
        #pragma unroll
        for (int mi = 0; mi < 2; mi++) {
            rc[mi][0] = sm[(SM_DEG >> 2) + wr * 32 + mi * 16 + g];
            rc[mi][1] = sm[(SM_DEG >> 2) + wr * 32 + mi * 16 + g + 8];
        }
        const __half* xwb = g_xw + ((size_t)bb * NN + row0) * FF;
        float* ob = out + ((size_t)bb * NN + row0) * FF;
        #pragma unroll
        for (int mi = 0; mi < 2; mi++) {
            int r0 = wr * 32 + mi * 16 + g;
            #pragma unroll
            for (int ni = 0; ni < 8; ni++) {
                int n = wc * 64 + ni * 8 + 2 * t;
                float2 x0 = __half22float2(*reinterpret_cast<const __half2*>(
                    xwb + (size_t)r0 * FF + n));
                float2 x1 = __half22float2(*reinterpret_cast<const __half2*>(
                    xwb + (size_t)(r0 + 8) * FF + n));
                float2 v0, v1;
                v0.x = fmaxf(acc[mi][ni][0] + x0.x, 0.f) * rc[mi][0];
                v0.y = fmaxf(acc[mi][ni][1] + x0.y, 0.f) * rc[mi][0];
                v1.x = fmaxf(acc[mi][ni][2] + x1.x, 0.f) * rc[mi][1];
                v1.y = fmaxf(acc[mi][ni][3] + x1.y, 0.f) * rc[mi][1];
                *reinterpret_cast<float2*>(ob + (size_t)r0 * FF + n) = v0;
                *reinterpret_cast<float2*>(ob + (size_t)(r0 + 8) * FF + n) = v1;
            }
        }
    }
}

// ============================ host ============================
extern "C" void kernel_launch(void* const* d_in, const int* in_sizes, int n_in,
                              void* d_out, int out_size) {
    const float* A = (const float*)d_in[0];   // relation_matrix [4,4096,4096]
    const float* X = (const float*)d_in[1];   // inputs          [4,4096,128]
    const float* w = (const float*)d_in[2];   // w               [128,128]
    float* out = (float*)d_out;               // [4,4096,128] fp32

    const int prep_smem = 2 * 128 * PX_STRIDE * 2;   // 69632 B
    cudaFuncSetAttribute(prep_xw_kernel,
                         cudaFuncAttributeMaxDynamicSharedMemorySize, prep_smem);
    cudaFuncSetAttribute(graphconv_main,
                         cudaFuncAttributeMaxDynamicSharedMemorySize, SMEM_MAIN);

    prep_xw_kernel<<<dim3(NN / 128, BB), 256, prep_smem>>>(X, w);
    graphconv_main<<<BB * 32, 256, SMEM_MAIN>>>(A, out);
}